// round 1
// baseline (speedup 1.0000x reference)
#include <cuda_runtime.h>
#include <math.h>

#define VOCAB   100000
#define EMB     256
#define NS      256
#define BATCH   16384

// ---------------------------------------------------------------------------
// Device globals (scratch — no allocations allowed)
// ---------------------------------------------------------------------------
__device__ int   g_is64;                 // 1 if index arrays are int64, 0 if int32
__device__ float g_rowsum[BATCH];        // per-example loss accumulator
__device__ float g_scratch[BATCH * EMB]; // fallback embed buffer if d_out layout差

// ---------------------------------------------------------------------------
// Index dtype detection: jnp.int64 silently becomes int32 unless x64 enabled.
// If the buffer really is int64 (values < 2^31), every odd 32-bit word is 0.
// 16 random ids in [0,100000) all being 0 is ~impossible, so this is safe.
// ---------------------------------------------------------------------------
__global__ void detect_dtype_kernel(const int* __restrict__ ids)
{
    if (threadIdx.x == 0) {
        int is64 = 1;
        #pragma unroll
        for (int k = 0; k < 16; k++) {
            if (ids[2 * k + 1] != 0) { is64 = 0; break; }
        }
        g_is64 = is64;
    }
}

__device__ __forceinline__ int load_id(const void* p, int i)
{
    if (g_is64) return (int)((const long long*)p)[i];
    return ((const int*)p)[i];
}

__device__ __forceinline__ float log_uniform_adj(int id)
{
    // log(NS * (log(id+2) - log(id+1)) / log(VOCAB+1))
    const float inv_log_range = 1.0f / logf((float)VOCAB + 1.0f);
    float lp = (logf((float)id + 2.0f) - logf((float)id + 1.0f)) * inv_log_range;
    return logf((float)NS * lp);
}

// softplus with the exact formulation of the reference:
//   xent(x, label=1) = max(x,0) - x + log1p(exp(-|x|))  == softplus(-x)
//   xent(x, label=0) = max(x,0)     + log1p(exp(-|x|))  == softplus(x)

// ---------------------------------------------------------------------------
// Kernel 1: gather embed rows (output #1) + true-label logits + true xent.
// One warp per batch row. 256 floats/row = 64 float4; lanes grab 2 each.
// ---------------------------------------------------------------------------
__global__ void gather_true_kernel(const float* __restrict__ embeddings,
                                   const float* __restrict__ nce_w,
                                   const float* __restrict__ nce_b,
                                   const void*  __restrict__ inputs,
                                   const void*  __restrict__ labels,
                                   float*       __restrict__ d_out,
                                   int use_dout)
{
    int warp = (blockIdx.x * blockDim.x + threadIdx.x) >> 5;
    int lane = threadIdx.x & 31;
    if (warp >= BATCH) return;

    float* embed_out = use_dout ? d_out : g_scratch;

    int id  = load_id(inputs, warp);
    int lab = load_id(labels, warp);

    const float4* e4 = (const float4*)(embeddings + (size_t)id  * EMB);
    const float4* w4 = (const float4*)(nce_w      + (size_t)lab * EMB);
    float4*       o4 = (float4*)(embed_out + (size_t)warp * EMB);

    float4 a0 = e4[lane];
    float4 a1 = e4[lane + 32];
    float4 b0 = w4[lane];
    float4 b1 = w4[lane + 32];
    o4[lane]      = a0;
    o4[lane + 32] = a1;

    float p = a0.x * b0.x + a0.y * b0.y + a0.z * b0.z + a0.w * b0.w
            + a1.x * b1.x + a1.y * b1.y + a1.z * b1.z + a1.w * b1.w;
    #pragma unroll
    for (int o = 16; o > 0; o >>= 1)
        p += __shfl_xor_sync(0xffffffffu, p, o);

    if (lane == 0) {
        float x = p + nce_b[lab] - log_uniform_adj(lab);
        // xent with label = 1
        g_rowsum[warp] = fmaxf(x, 0.0f) - x + log1pf(expf(-fabsf(x)));
    }
}

// ---------------------------------------------------------------------------
// Kernel 2: sampled-logits GEMM (16384x256 @ 256x256^T) fused with softplus
// epilogue and per-row accumulation. 64 batch rows per block, 256 threads,
// 4x4 microtile, 64x64x64 smem tiles.
// ---------------------------------------------------------------------------
__global__ void __launch_bounds__(256, 4)
sampled_gemm_kernel(const float* __restrict__ d_out,
                    const float* __restrict__ nce_w,
                    const float* __restrict__ nce_b,
                    const void*  __restrict__ sids,
                    int use_dout)
{
    __shared__ float Es[64][68];
    __shared__ float Ws[64][68];
    __shared__ int   s_id[NS];
    __shared__ float s_adj[NS];
    __shared__ float red[16][64];

    const float* embed = use_dout ? d_out : g_scratch;

    int t  = threadIdx.x;         // 0..255
    int tx = t & 15;              // col group
    int ty = t >> 4;              // row group
    int rb = blockIdx.x * 64;     // first batch row of this block

    if (t < NS) {
        int id = load_id(sids, t);
        s_id[t]  = id;
        s_adj[t] = nce_b[id] - log_uniform_adj(id);
    }
    __syncthreads();

    float rs[4] = {0.f, 0.f, 0.f, 0.f};

    #pragma unroll 1
    for (int cc = 0; cc < 4; cc++) {          // column tile (sampled ids)
        float acc[4][4] = {};
        #pragma unroll 1
        for (int kc = 0; kc < 4; kc++) {      // K tile
            __syncthreads();
            #pragma unroll
            for (int i = 0; i < 4; i++) {
                int v  = t + 256 * i;         // 0..1023 float4 slots
                int r  = v >> 4;              // 0..63
                int kv = v & 15;              // 0..15 (float4 within 64-K tile)
                float4 ev = *(const float4*)(embed + (size_t)(rb + r) * EMB
                                             + kc * 64 + kv * 4);
                *(float4*)&Es[r][kv * 4] = ev;
                int wrow  = s_id[cc * 64 + r];
                float4 wv = *(const float4*)(nce_w + (size_t)wrow * EMB
                                             + kc * 64 + kv * 4);
                *(float4*)&Ws[r][kv * 4] = wv;
            }
            __syncthreads();
            #pragma unroll
            for (int k = 0; k < 64; k++) {
                float a[4], b[4];
                #pragma unroll
                for (int i = 0; i < 4; i++) a[i] = Es[ty * 4 + i][k];
                #pragma unroll
                for (int j = 0; j < 4; j++) b[j] = Ws[tx * 4 + j][k];
                #pragma unroll
                for (int i = 0; i < 4; i++)
                    #pragma unroll
                    for (int j = 0; j < 4; j++)
                        acc[i][j] += a[i] * b[j];
            }
        }
        // epilogue: softplus(logit) with label = 0, accumulate per-row
        #pragma unroll
        for (int i = 0; i < 4; i++) {
            #pragma unroll
            for (int j = 0; j < 4; j++) {
                float x = acc[i][j] + s_adj[cc * 64 + tx * 4 + j];
                rs[i] += fmaxf(x, 0.0f) + log1pf(expf(-fabsf(x)));
            }
        }
    }

    // reduce across the 16 column-group threads owning each row (deterministic)
    #pragma unroll
    for (int i = 0; i < 4; i++) red[tx][ty * 4 + i] = rs[i];
    __syncthreads();
    if (t < 64) {
        float s = 0.0f;
        #pragma unroll
        for (int j = 0; j < 16; j++) s += red[j][t];
        g_rowsum[rb + t] += s;
    }
}

// ---------------------------------------------------------------------------
// Kernel 3: deterministic mean over g_rowsum -> d_out[out_idx]
// ---------------------------------------------------------------------------
__global__ void reduce_cost_kernel(float* __restrict__ d_out, int out_idx)
{
    __shared__ float sm[1024];
    int t = threadIdx.x;
    float s = 0.0f;
    for (int i = t; i < BATCH; i += 1024) s += g_rowsum[i];
    sm[t] = s;
    __syncthreads();
    #pragma unroll
    for (int o = 512; o > 0; o >>= 1) {
        if (t < o) sm[t] += sm[t + o];
        __syncthreads();
    }
    if (t == 0) d_out[out_idx] = sm[0] / (float)BATCH;
}

// ---------------------------------------------------------------------------
// Launch
// ---------------------------------------------------------------------------
extern "C" void kernel_launch(void* const* d_in, const int* in_sizes, int n_in,
                              void* d_out, int out_size)
{
    const float* embeddings = (const float*)d_in[0];
    const float* nce_w      = (const float*)d_in[1];
    const float* nce_b      = (const float*)d_in[2];
    const void*  inputs     = d_in[3];
    const void*  labels     = d_in[4];
    const void*  sids       = d_in[5];
    float*       out        = (float*)d_out;

    int use_dout = (out_size >= BATCH * EMB + 1) ? 1 : 0;

    detect_dtype_kernel<<<1, 32>>>((const int*)inputs);

    // 8 warps/block -> 8 rows/block -> 2048 blocks
    gather_true_kernel<<<BATCH / 8, 256>>>(embeddings, nce_w, nce_b,
                                           inputs, labels, out, use_dout);

    sampled_gemm_kernel<<<BATCH / 64, 256>>>(out, nce_w, nce_b, sids, use_dout);

    reduce_cost_kernel<<<1, 1024>>>(out, out_size - 1);
}

// round 2
// speedup vs baseline: 5.7558x; 5.7558x over previous
#include <cuda_runtime.h>
#include <cuda_bf16.h>
#include <math.h>
#include <stdint.h>

#define VOCAB   100000
#define EMB     256
#define NS      256
#define BATCH   16384

// ---------------------------------------------------------------------------
// Device globals (static scratch — no runtime allocation)
// ---------------------------------------------------------------------------
__device__ int            g_is64;
__device__ float          g_rowsum[BATCH];          // true-label xent per row
__device__ float          g_scratch[BATCH * EMB];   // fallback embed buffer
__device__ __nv_bfloat16  g_embed_bf[BATCH * EMB];  // bf16 copy of embed (GEMM A)
__device__ __nv_bfloat16  g_sw[NS * EMB];           // bf16 sampled weights (GEMM B)
__device__ float          g_adj[NS];                // bias - log(NS*prob) per sample
__device__ float          g_partial[BATCH / 128];   // per-GEMM-block loss partials

// ---------------------------------------------------------------------------
// Index dtype detection (jnp int64 may silently be int32)
// ---------------------------------------------------------------------------
__global__ void detect_dtype_kernel(const int* __restrict__ ids)
{
    if (threadIdx.x == 0) {
        int is64 = 1;
        #pragma unroll
        for (int k = 0; k < 16; k++)
            if (ids[2 * k + 1] != 0) { is64 = 0; break; }
        g_is64 = is64;
    }
}

__device__ __forceinline__ int load_id(const void* p, int i)
{
    if (g_is64) return (int)((const long long*)p)[i];
    return ((const int*)p)[i];
}

__device__ __forceinline__ float log_uniform_adj(int id)
{
    const float inv_log_range = 1.0f / logf((float)VOCAB + 1.0f);
    float lp = (logf((float)id + 2.0f) - logf((float)id + 1.0f)) * inv_log_range;
    return logf((float)NS * lp);
}

// softplus(x) = xent(x, label=0); softplus(-x) = xent(x, label=1)
__device__ __forceinline__ float softplus0(float x)
{
    return fmaxf(x, 0.0f) + log1pf(expf(-fabsf(x)));
}

// ---------------------------------------------------------------------------
// Kernel 1: gather embed rows (fp32 -> d_out, bf16 -> g_embed_bf)
//           + true-label logits + true xent into g_rowsum.
// One warp per batch row.
// ---------------------------------------------------------------------------
__global__ void gather_true_kernel(const float* __restrict__ embeddings,
                                   const float* __restrict__ nce_w,
                                   const float* __restrict__ nce_b,
                                   const void*  __restrict__ inputs,
                                   const void*  __restrict__ labels,
                                   float*       __restrict__ d_out,
                                   int use_dout)
{
    int warp = (blockIdx.x * blockDim.x + threadIdx.x) >> 5;
    int lane = threadIdx.x & 31;
    if (warp >= BATCH) return;

    float* embed_out = use_dout ? d_out : g_scratch;

    int id  = load_id(inputs, warp);
    int lab = load_id(labels, warp);

    const float4* e4 = (const float4*)(embeddings + (size_t)id  * EMB);
    const float4* w4 = (const float4*)(nce_w      + (size_t)lab * EMB);
    float4*       o4 = (float4*)(embed_out + (size_t)warp * EMB);

    float4 a0 = e4[lane];
    float4 a1 = e4[lane + 32];
    float4 b0 = w4[lane];
    float4 b1 = w4[lane + 32];
    o4[lane]      = a0;
    o4[lane + 32] = a1;

    // bf16 copy for the tensor-core GEMM
    {
        __nv_bfloat162 p0 = __floats2bfloat162_rn(a0.x, a0.y);
        __nv_bfloat162 p1 = __floats2bfloat162_rn(a0.z, a0.w);
        __nv_bfloat162 p2 = __floats2bfloat162_rn(a1.x, a1.y);
        __nv_bfloat162 p3 = __floats2bfloat162_rn(a1.z, a1.w);
        uint2* dst = (uint2*)(g_embed_bf + (size_t)warp * EMB);
        uint2 v0; v0.x = *(uint32_t*)&p0; v0.y = *(uint32_t*)&p1;
        uint2 v1; v1.x = *(uint32_t*)&p2; v1.y = *(uint32_t*)&p3;
        dst[lane]      = v0;   // cols [lane*4, lane*4+4)
        dst[lane + 32] = v1;   // cols [128 + lane*4, ...)
    }

    float p = a0.x * b0.x + a0.y * b0.y + a0.z * b0.z + a0.w * b0.w
            + a1.x * b1.x + a1.y * b1.y + a1.z * b1.z + a1.w * b1.w;
    #pragma unroll
    for (int o = 16; o > 0; o >>= 1)
        p += __shfl_xor_sync(0xffffffffu, p, o);

    if (lane == 0) {
        float x = p + nce_b[lab] - log_uniform_adj(lab);
        g_rowsum[warp] = softplus0(-x);   // label = 1
    }
}

// ---------------------------------------------------------------------------
// Kernel 1b: gather sampled weight rows -> bf16 g_sw, plus adjustment terms.
// One block per sampled id, 64 threads.
// ---------------------------------------------------------------------------
__global__ void prep_sampled_kernel(const float* __restrict__ nce_w,
                                    const float* __restrict__ nce_b,
                                    const void*  __restrict__ sids)
{
    int row = blockIdx.x;
    int t   = threadIdx.x;
    int id  = load_id(sids, row);

    float4 v = ((const float4*)(nce_w + (size_t)id * EMB))[t];
    __nv_bfloat162 p0 = __floats2bfloat162_rn(v.x, v.y);
    __nv_bfloat162 p1 = __floats2bfloat162_rn(v.z, v.w);
    uint2 packed; packed.x = *(uint32_t*)&p0; packed.y = *(uint32_t*)&p1;
    ((uint2*)(g_sw + (size_t)row * EMB))[t] = packed;

    if (t == 0)
        g_adj[row] = nce_b[id] - log_uniform_adj(id);
}

// ---------------------------------------------------------------------------
// Kernel 2: bf16 tensor-core GEMM 16384x256 @ (256x256)^T fused with
// softplus epilogue, per-row accumulation, and per-block loss reduction.
//
// Block: 128 rows x 256 cols (full N), 512 threads = 16 warps (4x4 grid),
// warp tile 32x64, mma.sync.m16n8k16 bf16. Entire A tile + B matrix resident
// in smem (no k-pipeline needed: K = 256 fits).
// ---------------------------------------------------------------------------
#define KPAD 264              // 256 + 8 bf16 padding -> conflict-free frags

__global__ void __launch_bounds__(512)
sampled_gemm_kernel(float* __restrict__ dummy)
{
    extern __shared__ char smem[];
    __nv_bfloat16* As   = (__nv_bfloat16*)smem;                        // 128*264
    __nv_bfloat16* Bs   = (__nv_bfloat16*)(smem + 67584);              // 256*264
    float*         adjs = (float*)(smem + 202752);                     // 256
    float*         red  = (float*)(smem + 203776);                     // 128*4
    float*         red2 = (float*)(smem + 205824);                     // 128

    const int t  = threadIdx.x;
    const int rb = blockIdx.x * 128;

    // ---- load A tile: 128 rows x 256 bf16 = 4096 uint4 ----
    {
        const uint4* src = (const uint4*)(g_embed_bf + (size_t)rb * EMB);
        #pragma unroll
        for (int i = 0; i < 8; i++) {
            int idx = t + 512 * i;            // uint4 index
            int r   = idx >> 5;               // 32 uint4 per row
            int c   = idx & 31;
            *(uint4*)(As + r * KPAD + c * 8) = src[r * 32 + c];
        }
    }
    // ---- load B: 256 rows x 256 bf16 = 8192 uint4 ----
    {
        const uint4* src = (const uint4*)g_sw;
        #pragma unroll
        for (int i = 0; i < 16; i++) {
            int idx = t + 512 * i;
            int r   = idx >> 5;
            int c   = idx & 31;
            *(uint4*)(Bs + r * KPAD + c * 8) = src[r * 32 + c];
        }
    }
    if (t < NS) adjs[t] = g_adj[t];
    __syncthreads();

    const int wid    = t >> 5;
    const int lane   = t & 31;
    const int warp_m = (wid >> 2) * 32;   // 0,32,64,96
    const int warp_n = (wid & 3) * 64;    // 0,64,128,192
    const int group  = lane >> 2;
    const int tig    = lane & 3;

    float c[2][8][4];
    #pragma unroll
    for (int mt = 0; mt < 2; mt++)
        #pragma unroll
        for (int nt = 0; nt < 8; nt++)
            #pragma unroll
            for (int q = 0; q < 4; q++) c[mt][nt][q] = 0.0f;

    const __nv_bfloat16* arow = As + (warp_m + group) * KPAD + tig * 2;
    const __nv_bfloat16* brow = Bs + (warp_n + group) * KPAD + tig * 2;

    #pragma unroll 4
    for (int kk = 0; kk < 16; kk++) {
        const int k0 = kk * 16;
        uint32_t a[2][4], b[8][2];
        #pragma unroll
        for (int mt = 0; mt < 2; mt++) {
            const __nv_bfloat16* p = arow + mt * 16 * KPAD + k0;
            a[mt][0] = *(const uint32_t*)(p);
            a[mt][1] = *(const uint32_t*)(p + 8 * KPAD);
            a[mt][2] = *(const uint32_t*)(p + 8);
            a[mt][3] = *(const uint32_t*)(p + 8 * KPAD + 8);
        }
        #pragma unroll
        for (int nt = 0; nt < 8; nt++) {
            const __nv_bfloat16* p = brow + nt * 8 * KPAD + k0;
            b[nt][0] = *(const uint32_t*)(p);
            b[nt][1] = *(const uint32_t*)(p + 8);
        }
        #pragma unroll
        for (int mt = 0; mt < 2; mt++)
            #pragma unroll
            for (int nt = 0; nt < 8; nt++)
                asm volatile(
                    "mma.sync.aligned.m16n8k16.row.col.f32.bf16.bf16.f32 "
                    "{%0,%1,%2,%3}, {%4,%5,%6,%7}, {%8,%9}, {%0,%1,%2,%3};"
                    : "+f"(c[mt][nt][0]), "+f"(c[mt][nt][1]),
                      "+f"(c[mt][nt][2]), "+f"(c[mt][nt][3])
                    : "r"(a[mt][0]), "r"(a[mt][1]), "r"(a[mt][2]), "r"(a[mt][3]),
                      "r"(b[nt][0]), "r"(b[nt][1]));
    }

    // ---- epilogue: softplus + row sums ----
    // thread owns rows {warp_m + mt*16 + group, +8}, cols {warp_n + nt*8 + tig*2, +1}
    float rs[2][2] = {{0.f, 0.f}, {0.f, 0.f}};   // [mt][half]
    #pragma unroll
    for (int mt = 0; mt < 2; mt++) {
        #pragma unroll
        for (int nt = 0; nt < 8; nt++) {
            int n0 = warp_n + nt * 8 + tig * 2;
            float adj0 = adjs[n0], adj1 = adjs[n0 + 1];
            rs[mt][0] += softplus0(c[mt][nt][0] + adj0)
                       + softplus0(c[mt][nt][1] + adj1);
            rs[mt][1] += softplus0(c[mt][nt][2] + adj0)
                       + softplus0(c[mt][nt][3] + adj1);
        }
    }
    // reduce across the 4 tig lanes (same rows, disjoint columns)
    #pragma unroll
    for (int mt = 0; mt < 2; mt++)
        #pragma unroll
        for (int h = 0; h < 2; h++) {
            rs[mt][h] += __shfl_xor_sync(0xffffffffu, rs[mt][h], 1);
            rs[mt][h] += __shfl_xor_sync(0xffffffffu, rs[mt][h], 2);
        }
    if (tig == 0) {
        int wc = wid & 3;
        red[(warp_m + group)      * 4 + wc] = rs[0][0];
        red[(warp_m + group + 8)  * 4 + wc] = rs[0][1];
        red[(warp_m + group + 16) * 4 + wc] = rs[1][0];
        red[(warp_m + group + 24) * 4 + wc] = rs[1][1];
    }
    __syncthreads();

    // per-row total (256 cols) + true xent, then block reduce -> partial
    if (t < 128) {
        float s = red[t * 4] + red[t * 4 + 1] + red[t * 4 + 2] + red[t * 4 + 3]
                + g_rowsum[rb + t];
        red2[t] = s;
    }
    __syncthreads();
    #pragma unroll
    for (int o = 64; o > 0; o >>= 1) {
        if (t < o) red2[t] += red2[t + o];
        __syncthreads();
    }
    if (t == 0) g_partial[blockIdx.x] = red2[0];
}

// ---------------------------------------------------------------------------
// Kernel 3: sum 128 block partials -> mean cost
// ---------------------------------------------------------------------------
__global__ void reduce_cost_kernel(float* __restrict__ d_out, int out_idx)
{
    __shared__ float sm[128];
    int t = threadIdx.x;
    sm[t] = g_partial[t];
    __syncthreads();
    #pragma unroll
    for (int o = 64; o > 0; o >>= 1) {
        if (t < o) sm[t] += sm[t + o];
        __syncthreads();
    }
    if (t == 0) d_out[out_idx] = sm[0] / (float)BATCH;
}

// ---------------------------------------------------------------------------
// Launch
// ---------------------------------------------------------------------------
extern "C" void kernel_launch(void* const* d_in, const int* in_sizes, int n_in,
                              void* d_out, int out_size)
{
    const float* embeddings = (const float*)d_in[0];
    const float* nce_w      = (const float*)d_in[1];
    const float* nce_b      = (const float*)d_in[2];
    const void*  inputs     = d_in[3];
    const void*  labels     = d_in[4];
    const void*  sids       = d_in[5];
    float*       out        = (float*)d_out;

    int use_dout = (out_size >= BATCH * EMB + 1) ? 1 : 0;

    static int smem_set = 0;
    if (!smem_set) {
        cudaFuncSetAttribute(sampled_gemm_kernel,
                             cudaFuncAttributeMaxDynamicSharedMemorySize,
                             206336);
        smem_set = 1;
    }

    detect_dtype_kernel<<<1, 32>>>((const int*)inputs);

    gather_true_kernel<<<BATCH / 8, 256>>>(embeddings, nce_w, nce_b,
                                           inputs, labels, out, use_dout);

    prep_sampled_kernel<<<NS, 64>>>(nce_w, nce_b, sids);

    sampled_gemm_kernel<<<BATCH / 128, 512, 206336>>>(out);

    reduce_cost_kernel<<<1, 128>>>(out, out_size - 1);
}